// round 9
// baseline (speedup 1.0000x reference)
#include <cuda_runtime.h>
#include <cooperative_groups.h>
#include <math.h>
#include <stdint.h>

namespace cg = cooperative_groups;

#define S_LEN 4096
#define D_DIM 300
#define HU    150
#define HH    300      // biLSTM concat dim
#define Z_DIM 600      // 4*HU
#define NSYN  4

// ---------------- scratch (static device memory; no allocation) ----------------
__device__ float g_emb[S_LEN * D_DIM];
__device__ float g_Zf[S_LEN * Z_DIM];
__device__ float g_Zb[S_LEN * Z_DIM];
__device__ float g_hidden[S_LEN * HH];
__device__ float g_Pout[S_LEN * HH];
__device__ float g_m[S_LEN * D_DIM];
__device__ float g_coeff[S_LEN];
__device__ float g_HHAT[2 * HH];

// ---------------- small PTX helpers ----------------
__device__ __forceinline__ uint32_t smem_u32(const void* p) {
    return (uint32_t)__cvta_generic_to_shared(p);
}
__device__ __forceinline__ void mbar_init(uint32_t a, uint32_t cnt) {
    asm volatile("mbarrier.init.shared.b64 [%0], %1;" ::"r"(a), "r"(cnt) : "memory");
}
__device__ __forceinline__ uint32_t mapa_shared(uint32_t a, uint32_t rank) {
    uint32_t r;
    asm("mapa.shared::cluster.u32 %0, %1, %2;" : "=r"(r) : "r"(a), "r"(rank));
    return r;
}
// bulk DSMEM copy: local smem -> peer CTA smem, crediting peer's mbarrier with tx bytes
__device__ __forceinline__ void bulk_copy_s2c(uint32_t dst, uint32_t src, uint32_t bytes,
                                              uint32_t rmbar) {
    asm volatile(
        "cp.async.bulk.shared::cluster.shared::cta.mbarrier::complete_tx::bytes [%0], [%1], %2, [%3];"
        ::"r"(dst), "r"(src), "r"(bytes), "r"(rmbar) : "memory");
}
__device__ __forceinline__ void fence_proxy_async_cta() {
    asm volatile("fence.proxy.async.shared::cta;" ::: "memory");
}
__device__ __forceinline__ void mbar_expect_tx(uint32_t a, uint32_t bytes) {
    asm volatile("mbarrier.arrive.expect_tx.shared::cta.b64 _, [%0], %1;"
                 ::"r"(a), "r"(bytes) : "memory");
}
__device__ __forceinline__ void mbar_wait(uint32_t a, uint32_t parity) {
    uint32_t done;
    asm volatile(
        "{\n\t.reg .pred p;\n\t"
        "mbarrier.try_wait.parity.acquire.cluster.shared::cta.b64 p, [%1], %2;\n\t"
        "selp.b32 %0,1,0,p;\n\t}"
        : "=r"(done) : "r"(a), "r"(parity) : "memory");
    while (!done) {
        asm volatile(
            "{\n\t.reg .pred p;\n\t"
            "mbarrier.try_wait.parity.acquire.cluster.shared::cta.b64 p, [%1], %2, 0x989680;\n\t"
            "selp.b32 %0,1,0,p;\n\t}"
            : "=r"(done) : "r"(a), "r"(parity) : "memory");
    }
}
__device__ __forceinline__ float fsig(float x) {
    return __fdividef(1.f, 1.f + __expf(-x));
}
__device__ __forceinline__ float ftanh(float x) {
    float e = __expf(2.f * x);
    return 1.f - __fdividef(2.f, e + 1.f);
}
__device__ __forceinline__ void fma_f32x2(unsigned long long& d, unsigned long long a,
                                          unsigned long long b, unsigned long long c) {
    asm("fma.rn.f32x2 %0, %1, %2, %3;" : "=l"(d) : "l"(a), "l"(b), "l"(c));
}
__device__ __forceinline__ unsigned long long pack2(float lo, float hi) {
    return ((unsigned long long)__float_as_uint(hi) << 32) | (unsigned long long)__float_as_uint(lo);
}

// ---------------- embedding gather ----------------
__global__ void k_gather(const int* __restrict__ sentence, const float* __restrict__ E) {
    int s = blockIdx.x;
    const float* src = E + (size_t)sentence[s] * D_DIM;
    float* dst = g_emb + (size_t)s * D_DIM;
    for (int d = threadIdx.x; d < D_DIM; d += blockDim.x) dst[d] = src[d];
}

// ---------------- fp32 tiled GEMM: C[M,N] = A[M,K] @ B[K,N] + bias ----------------
#define BM 64
#define BN 64
#define BK 16

template <int M, int N, int K, int REV>
__device__ __forceinline__ void gemm_body(const float* __restrict__ A,
                                          const float* __restrict__ B,
                                          const float* __restrict__ bias,
                                          float* __restrict__ C) {
    __shared__ float As[BM][BK + 1];
    __shared__ float Bs[BK][BN];
    const int tx = threadIdx.x, ty = threadIdx.y;
    const int tid = ty * 16 + tx;
    const int m0 = blockIdx.y * BM, n0 = blockIdx.x * BN;

    float acc[4][4];
#pragma unroll
    for (int i = 0; i < 4; i++)
#pragma unroll
        for (int j = 0; j < 4; j++) acc[i][j] = 0.f;

    for (int k0 = 0; k0 < K; k0 += BK) {
#pragma unroll
        for (int l = 0; l < 4; l++) {
            int idx = tid + l * 256;
            int r = idx >> 4;
            int c = idx & 15;
            int gr = m0 + r;
            int gc = k0 + c;
            float v = 0.f;
            if (gc < K && gr < M) {
                int ar = REV ? (M - 1 - gr) : gr;
                v = A[(size_t)ar * K + gc];
            }
            As[r][c] = v;
        }
#pragma unroll
        for (int l = 0; l < 4; l++) {
            int idx = tid + l * 256;
            int r = idx >> 6;
            int c = idx & 63;
            int gk = k0 + r, gn = n0 + c;
            float v = 0.f;
            if (gk < K && gn < N) v = B[(size_t)gk * N + gn];
            Bs[r][c] = v;
        }
        __syncthreads();
#pragma unroll
        for (int kk = 0; kk < BK; kk++) {
            float a0 = As[ty * 4 + 0][kk];
            float a1 = As[ty * 4 + 1][kk];
            float a2 = As[ty * 4 + 2][kk];
            float a3 = As[ty * 4 + 3][kk];
            float4 b4 = *reinterpret_cast<const float4*>(&Bs[kk][tx * 4]);
            acc[0][0] = fmaf(a0, b4.x, acc[0][0]); acc[0][1] = fmaf(a0, b4.y, acc[0][1]);
            acc[0][2] = fmaf(a0, b4.z, acc[0][2]); acc[0][3] = fmaf(a0, b4.w, acc[0][3]);
            acc[1][0] = fmaf(a1, b4.x, acc[1][0]); acc[1][1] = fmaf(a1, b4.y, acc[1][1]);
            acc[1][2] = fmaf(a1, b4.z, acc[1][2]); acc[1][3] = fmaf(a1, b4.w, acc[1][3]);
            acc[2][0] = fmaf(a2, b4.x, acc[2][0]); acc[2][1] = fmaf(a2, b4.y, acc[2][1]);
            acc[2][2] = fmaf(a2, b4.z, acc[2][2]); acc[2][3] = fmaf(a2, b4.w, acc[2][3]);
            acc[3][0] = fmaf(a3, b4.x, acc[3][0]); acc[3][1] = fmaf(a3, b4.y, acc[3][1]);
            acc[3][2] = fmaf(a3, b4.z, acc[3][2]); acc[3][3] = fmaf(a3, b4.w, acc[3][3]);
        }
        __syncthreads();
    }
#pragma unroll
    for (int i = 0; i < 4; i++) {
        int gr = m0 + ty * 4 + i;
        if (gr < M) {
#pragma unroll
            for (int j = 0; j < 4; j++) {
                int gn = n0 + tx * 4 + j;
                if (gn < N) C[(size_t)gr * N + gn] = acc[i][j] + bias[gn];
            }
        }
    }
}

__global__ void k_gemm_Zf(const float* __restrict__ W, const float* __restrict__ b) {
    gemm_body<S_LEN, Z_DIM, D_DIM, 0>(g_emb, W, b, g_Zf);
}
__global__ void k_gemm_Zb(const float* __restrict__ W, const float* __restrict__ b) {
    gemm_body<S_LEN, Z_DIM, D_DIM, 1>(g_emb, W, b, g_Zb);
}
__global__ void k_gemm_P(const float* __restrict__ W, const float* __restrict__ b) {
    gemm_body<S_LEN, HH, HH, 0>(g_hidden, W, b, g_Pout);
}

// ---------------- LSTM recurrence: 2 clusters (fwd/bwd) of 6 CTAs ----------------
// Per step: owners STS their h into a 112B staging buffer; one __syncthreads; tid0
// issues SIX cp.async.bulk DSMEM copies (one per peer, 112B each) that credit each
// peer's mbarrier via complete_tx. Consumers post expect_tx(672) and do one local
// wait. 6 tx events per consumer per step (vs 78 with per-owner st.async).
// h layout: per-source stride padded to 28 floats (112B, 16B-aligned for bulk copy).
#define GCL    6
#define UPC    25
#define OPC    100
#define SRC_STRIDE 28            // padded slots per source CTA (112 bytes)
#define HPAD   176               // 6*28 = 168 used, pad to 176 (16B-aligned lanes: 4*44)
#define KCH    44                // padded slots per lane (4*44 = 176)
#define KP2    22
#define LSTM_T 416
#define EXP_TX (GCL * SRC_STRIDE * 4)   // 672 bytes per consumer per step

__global__ __launch_bounds__(LSTM_T, 1) __cluster_dims__(GCL, 1, 1)
void k_lstm(const float* __restrict__ Uf, const float* __restrict__ Ub) {
    cg::cluster_group cluster = cg::this_cluster();
    const int rank = (int)cluster.block_rank();
    const int dir = blockIdx.x / GCL;  // 0 = fwd, 1 = bwd
    const float* __restrict__ Z = (dir == 0) ? g_Zf : g_Zb;
    const float* __restrict__ U = (dir == 0) ? Uf : Ub;

    __shared__ __align__(16) float h_sh[2][HPAD];        // double-buffered padded h
    __shared__ __align__(16) float h_stage[SRC_STRIDE];  // local staging (25 used)
    __shared__ __align__(8) uint64_t mb[2];
    __shared__ uint32_t tab[3 * GCL];  // [0..5] peer dst base, [6..11] mb0, [12..17] mb1

    const int tid = threadIdx.x;
    const int o_local = tid >> 2;             // 0..103
    const int lg = tid & 3;
    const bool active = (o_local < OPC);
    const int u = o_local >> 2;               // local unit 0..24
    const int g = o_local & 3;                // gate 0..3 (i,f,g,o)
    int j = g * HU + rank * UPC + u;          // column in [0,600)
    if (!active) j = 0;
    const int k0 = lg * KCH;                  // padded-slot base for this lane
    const bool owner = active && ((tid & 15) == 0);  // lanes 0/16 of warps 0..12
    const int lane = tid & 31;

    // U slice in registers, indexed by PADDED slot: slot s -> source rank s/28,
    // local unit s%28 (s%28 >= 25 and s >= 168 are padding; U=0, h stays 0).
    unsigned long long U2[KP2];
#pragma unroll
    for (int i = 0; i < KP2; i++) {
        float v[2];
#pragma unroll
        for (int q = 0; q < 2; q++) {
            int s = k0 + 2 * i + q;
            int sr = s / SRC_STRIDE, su = s - sr * SRC_STRIDE;
            bool valid = active && sr < GCL && su < UPC;
            v[q] = valid ? U[(size_t)(sr * UPC + su) * Z_DIM + j] : 0.f;
        }
        U2[i] = pack2(v[0], v[1]);
    }

    for (int k = tid; k < 2 * HPAD; k += blockDim.x) (&h_sh[0][0])[k] = 0.f;
    if (tid < SRC_STRIDE) h_stage[tid] = 0.f;  // slots 25..27 stay 0 forever

    const uint32_t m0 = smem_u32(&mb[0]), m1 = smem_u32(&mb[1]);
    const uint32_t hbase = smem_u32(&h_sh[0][0]);
    const uint32_t stage = smem_u32(&h_stage[0]);
    if (tid == 0) {
        mbar_init(m0, 1);  // sole arrival = the expect_tx post; completion via tx bytes
        mbar_init(m1, 1);
    }
    if (tid < GCL) {  // address table: peer dst base (incl. this CTA's slot) + mbars
        tab[tid] = mapa_shared(hbase, tid) + (uint32_t)(rank * SRC_STRIDE * 4);
        tab[GCL + tid] = mapa_shared(m0, tid);
        tab[2 * GCL + tid] = mapa_shared(m1, tid);
    }

    float c = 0.f;
    int ph0 = 0, ph1 = 0;

    cluster.sync();  // mbar init + zeroed buffers + address table visible

    float zcur = (active && lg == 0) ? __ldg(&Z[j]) : 0.f;
    const int base = lane & 16;

    for (int t = 0; t < S_LEN; t++) {
        const int b = t & 1;
        const int nb = (t + 1) & 1;
        if (t) {
            if (b) {
                if (tid == 0) mbar_expect_tx(m1, EXP_TX);
                mbar_wait(m1, ph1); ph1 ^= 1;
            } else {
                if (tid == 0) mbar_expect_tx(m0, EXP_TX);
                mbar_wait(m0, ph0); ph0 ^= 1;
            }
        }
        // ---- dot over padded h buffer (packed f32x2 FMA) ----
        const ulonglong2* hp = reinterpret_cast<const ulonglong2*>(&h_sh[b][k0]);
        unsigned long long a0 = 0ull, a1 = 0ull;
#pragma unroll
        for (int i = 0; i < KP2 / 2; i++) {
            ulonglong2 hv = hp[i];
            fma_f32x2(a0, U2[2 * i + 0], hv.x, a0);
            fma_f32x2(a1, U2[2 * i + 1], hv.y, a1);
        }
        unsigned long long as;
        asm("add.rn.f32x2 %0, %1, %2;" : "=l"(as) : "l"(a0), "l"(a1));
        float acc = __uint_as_float((uint32_t)as) + __uint_as_float((uint32_t)(as >> 32));
        acc += __shfl_xor_sync(0xffffffffu, acc, 1);
        acc += __shfl_xor_sync(0xffffffffu, acc, 2);
        float zfull = zcur + acc;
        if (active && lg == 0 && t + 1 < S_LEN) zcur = __ldg(&Z[(size_t)(t + 1) * Z_DIM + j]);

        // per-gate activation on lg==0 lanes (parallel MUFU, off the owner chain)
        float act = 0.f;
        if (active && lg == 0) act = (g == 2) ? ftanh(zfull) : fsig(zfull);

        // collect activated gates onto owner lanes (0 and 16)
        float fg = __shfl_sync(0xffffffffu, act, base + 4);
        float gg = __shfl_sync(0xffffffffu, act, base + 8);
        float og = __shfl_sync(0xffffffffu, act, base + 12);

        if (owner) {
            c = fg * c + act * gg;
            float hval = og * ftanh(c);
            h_stage[u] = hval;  // STS into staging buffer
            int s_out = (dir == 0) ? t : (S_LEN - 1 - t);
            g_hidden[(size_t)s_out * HH + dir * HU + rank * UPC + u] = hval;
        }
        // local barrier: orders all reads of h_sh[b] and owners' STS before the copy
        __syncthreads();
        if (tid == 0 && t + 1 < S_LEN) {
            fence_proxy_async_cta();  // make STS visible to the async proxy
            const uint32_t boff = (uint32_t)nb * (HPAD * 4u);
            const int moff = nb ? 2 * GCL : GCL;
#pragma unroll
            for (int r = 0; r < GCL; r++)
                bulk_copy_s2c(tab[r] + boff, stage, SRC_STRIDE * 4, tab[moff + r]);
        }
    }
}

// ---------------- primary attention (per word) + secondary attention coeff ----------------
__global__ void k_attn(const int* __restrict__ syn, const float* __restrict__ E,
                       const float* __restrict__ Ws, const float* __restrict__ bs) {
    int s = blockIdx.x;
    int tid = threadIdx.x;  // 128
    int warp = tid >> 5, lane = tid & 31;
    __shared__ float sc[NSYN];
    __shared__ int idx[NSYN];
    __shared__ float red[128];
    if (s == 0) {  // zero the H_HAT accumulator (consumed by k_hhat after this kernel)
        for (int k = tid; k < 2 * HH; k += 128) g_HHAT[k] = 0.f;
    }
    if (tid < NSYN) idx[tid] = syn[s * NSYN + tid];
    __syncthreads();
    {
        const float* sy = E + (size_t)idx[warp] * D_DIM;
        const float* po = g_Pout + (size_t)s * HH;
        float d0 = 0.f;
        for (int d = lane; d < D_DIM; d += 32) d0 = fmaf(po[d], sy[d], d0);
#pragma unroll
        for (int o = 16; o; o >>= 1) d0 += __shfl_xor_sync(0xffffffffu, d0, o);
        if (lane == 0) sc[warp] = __expf(d0);
    }
    __syncthreads();
    const float* e0 = E + (size_t)idx[0] * D_DIM;
    const float* e1 = E + (size_t)idx[1] * D_DIM;
    const float* e2 = E + (size_t)idx[2] * D_DIM;
    const float* e3 = E + (size_t)idx[3] * D_DIM;
    float s0 = sc[0], s1 = sc[1], s2 = sc[2], s3 = sc[3];
    float ca = 0.f;
    for (int d = tid; d < D_DIM; d += 128) {
        float md = s0 * e0[d] + s1 * e1[d] + s2 * e2[d] + s3 * e3[d];
        g_m[(size_t)s * D_DIM + d] = md;
        ca = fmaf(md, Ws[HH + d], ca);
        ca = fmaf(g_hidden[(size_t)s * HH + d], Ws[d], ca);
    }
    red[tid] = ca;
    __syncthreads();
    for (int o = 64; o; o >>= 1) {
        if (tid < o) red[tid] += red[tid + o];
        __syncthreads();
    }
    if (tid == 0) g_coeff[s] = __expf(tanhf(red[0] + bs[0]));
}

// ---------------- H_HAT[j] = sum_s coeff[s] * h_hats[s][j]  (parallel over s) ----------------
#define HH_BLOCKS 64
#define HH_SPB (S_LEN / HH_BLOCKS)
__global__ void k_hhat() {
    int jj = threadIdx.x;  // 0..599
    int s0 = blockIdx.x * HH_SPB;
    const float* src = (jj < HH) ? (g_hidden + jj) : (g_m + (jj - HH));
    float acc = 0.f;
#pragma unroll 4
    for (int s = s0; s < s0 + HH_SPB; s++)
        acc = fmaf(g_coeff[s], src[(size_t)s * HH], acc);
    atomicAdd(&g_HHAT[jj], acc);
}

// ---------------- output heads ----------------
__global__ void k_heads(const float* __restrict__ We, const float* __restrict__ be,
                        const float* __restrict__ Wse, const float* __restrict__ bse,
                        float* __restrict__ out) {
    int tid = threadIdx.x;
    if (tid < 8) {
        float a = 0.f;
        for (int jj = 0; jj < 2 * HH; jj++) a = fmaf(g_HHAT[jj], We[jj * 8 + tid], a);
        out[tid] = a + be[tid];
    } else if (tid == 8) {
        float a = 0.f;
        for (int jj = 0; jj < 2 * HH; jj++) a = fmaf(g_HHAT[jj], Wse[jj], a);
        out[8] = a + bse[0];
    }
}

// ---------------- launch ----------------
extern "C" void kernel_launch(void* const* d_in, const int* in_sizes, int n_in,
                              void* d_out, int out_size) {
    const int* sentence = (const int*)d_in[0];
    const int* syn = (const int*)d_in[1];
    const float* E = (const float*)d_in[2];
    const float* W_f = (const float*)d_in[3];
    const float* U_f = (const float*)d_in[4];
    const float* b_f = (const float*)d_in[5];
    const float* W_b = (const float*)d_in[6];
    const float* U_b = (const float*)d_in[7];
    const float* b_b = (const float*)d_in[8];
    const float* W_p = (const float*)d_in[9];
    const float* b_p = (const float*)d_in[10];
    const float* W_s = (const float*)d_in[11];
    const float* b_s = (const float*)d_in[12];
    const float* W_emo = (const float*)d_in[13];
    const float* b_emo = (const float*)d_in[14];
    const float* W_sent = (const float*)d_in[15];
    const float* b_sent = (const float*)d_in[16];
    float* out = (float*)d_out;

    k_gather<<<S_LEN, 128>>>(sentence, E);

    dim3 blk(16, 16);
    dim3 gz((Z_DIM + BN - 1) / BN, (S_LEN + BM - 1) / BM);
    k_gemm_Zf<<<gz, blk>>>(W_f, b_f);
    k_gemm_Zb<<<gz, blk>>>(W_b, b_b);

    k_lstm<<<2 * GCL, LSTM_T>>>(U_f, U_b);

    dim3 gp((HH + BN - 1) / BN, (S_LEN + BM - 1) / BM);
    k_gemm_P<<<gp, blk>>>(W_p, b_p);

    k_attn<<<S_LEN, 128>>>(syn, E, W_s, b_s);
    k_hhat<<<HH_BLOCKS, 2 * HH>>>();
    k_heads<<<1, 32>>>(W_emo, b_emo, W_sent, b_sent, out);
}

// round 14
// speedup vs baseline: 1.5810x; 1.5810x over previous
#include <cuda_runtime.h>
#include <cooperative_groups.h>
#include <math.h>
#include <stdint.h>

namespace cg = cooperative_groups;

#define S_LEN 4096
#define D_DIM 300
#define HU    150
#define HH    300      // biLSTM concat dim
#define Z_DIM 600      // 4*HU
#define NSYN  4

// ---------------- scratch (static device memory; no allocation) ----------------
__device__ float g_emb[S_LEN * D_DIM];
__device__ float g_Zf[S_LEN * Z_DIM];
__device__ float g_Zb[S_LEN * Z_DIM];
__device__ float g_hidden[S_LEN * HH];
__device__ float g_Pout[S_LEN * HH];
__device__ float g_m[S_LEN * D_DIM];
__device__ float g_coeff[S_LEN];
__device__ float g_HHAT[2 * HH];

// ---------------- small PTX helpers ----------------
__device__ __forceinline__ uint32_t smem_u32(const void* p) {
    return (uint32_t)__cvta_generic_to_shared(p);
}
__device__ __forceinline__ void mbar_init(uint32_t a, uint32_t cnt) {
    asm volatile("mbarrier.init.shared.b64 [%0], %1;" ::"r"(a), "r"(cnt) : "memory");
}
__device__ __forceinline__ uint32_t mapa_shared(uint32_t a, uint32_t rank) {
    uint32_t r;
    asm("mapa.shared::cluster.u32 %0, %1, %2;" : "=r"(r) : "r"(a), "r"(rank));
    return r;
}
// fused remote store + barrier tx credit, 16 bytes
__device__ __forceinline__ void st_async_v4(uint32_t ra, float x, float y, float z, float w,
                                            uint32_t rmbar) {
    asm volatile(
        "st.async.shared::cluster.mbarrier::complete_tx::bytes.v4.b32 [%0], {%1,%2,%3,%4}, [%5];"
        ::"r"(ra), "f"(x), "f"(y), "f"(z), "f"(w), "r"(rmbar) : "memory");
}
// fused remote store + barrier tx credit, 4 bytes
__device__ __forceinline__ void st_async_b32(uint32_t ra, float v, uint32_t rmbar) {
    asm volatile(
        "st.async.shared::cluster.mbarrier::complete_tx::bytes.b32 [%0], %1, [%2];"
        ::"r"(ra), "f"(v), "r"(rmbar) : "memory");
}
__device__ __forceinline__ void mbar_expect_tx(uint32_t a, uint32_t bytes) {
    asm volatile("mbarrier.arrive.expect_tx.shared::cta.b64 _, [%0], %1;"
                 ::"r"(a), "r"(bytes) : "memory");
}
__device__ __forceinline__ void mbar_wait(uint32_t a, uint32_t parity) {
    uint32_t done;
    asm volatile(
        "{\n\t.reg .pred p;\n\t"
        "mbarrier.try_wait.parity.acquire.cluster.shared::cta.b64 p, [%1], %2;\n\t"
        "selp.b32 %0,1,0,p;\n\t}"
        : "=r"(done) : "r"(a), "r"(parity) : "memory");
    while (!done) {
        asm volatile(
            "{\n\t.reg .pred p;\n\t"
            "mbarrier.try_wait.parity.acquire.cluster.shared::cta.b64 p, [%1], %2, 0x989680;\n\t"
            "selp.b32 %0,1,0,p;\n\t}"
            : "=r"(done) : "r"(a), "r"(parity) : "memory");
    }
}
__device__ __forceinline__ float fsig(float x) {
    return __fdividef(1.f, 1.f + __expf(-x));
}
__device__ __forceinline__ float ftanh(float x) {
    float e = __expf(2.f * x);
    return 1.f - __fdividef(2.f, e + 1.f);
}
__device__ __forceinline__ void fma_f32x2(unsigned long long& d, unsigned long long a,
                                          unsigned long long b, unsigned long long c) {
    asm("fma.rn.f32x2 %0, %1, %2, %3;" : "=l"(d) : "l"(a), "l"(b), "l"(c));
}
__device__ __forceinline__ unsigned long long pack2(float lo, float hi) {
    return ((unsigned long long)__float_as_uint(hi) << 32) | (unsigned long long)__float_as_uint(lo);
}

// ---------------- embedding gather ----------------
__global__ void k_gather(const int* __restrict__ sentence, const float* __restrict__ E) {
    int s = blockIdx.x;
    const float* src = E + (size_t)sentence[s] * D_DIM;
    float* dst = g_emb + (size_t)s * D_DIM;
    for (int d = threadIdx.x; d < D_DIM; d += blockDim.x) dst[d] = src[d];
}

// ---------------- fp32 tiled GEMM: C[M,N] = A[M,K] @ B[K,N] + bias ----------------
#define BM 64
#define BN 64
#define BK 16

template <int M, int N, int K, int REV>
__device__ __forceinline__ void gemm_body(const float* __restrict__ A,
                                          const float* __restrict__ B,
                                          const float* __restrict__ bias,
                                          float* __restrict__ C) {
    __shared__ float As[BM][BK + 1];
    __shared__ float Bs[BK][BN];
    const int tx = threadIdx.x, ty = threadIdx.y;
    const int tid = ty * 16 + tx;
    const int m0 = blockIdx.y * BM, n0 = blockIdx.x * BN;

    float acc[4][4];
#pragma unroll
    for (int i = 0; i < 4; i++)
#pragma unroll
        for (int j = 0; j < 4; j++) acc[i][j] = 0.f;

    for (int k0 = 0; k0 < K; k0 += BK) {
#pragma unroll
        for (int l = 0; l < 4; l++) {
            int idx = tid + l * 256;
            int r = idx >> 4;
            int c = idx & 15;
            int gr = m0 + r;
            int gc = k0 + c;
            float v = 0.f;
            if (gc < K && gr < M) {
                int ar = REV ? (M - 1 - gr) : gr;
                v = A[(size_t)ar * K + gc];
            }
            As[r][c] = v;
        }
#pragma unroll
        for (int l = 0; l < 4; l++) {
            int idx = tid + l * 256;
            int r = idx >> 6;
            int c = idx & 63;
            int gk = k0 + r, gn = n0 + c;
            float v = 0.f;
            if (gk < K && gn < N) v = B[(size_t)gk * N + gn];
            Bs[r][c] = v;
        }
        __syncthreads();
#pragma unroll
        for (int kk = 0; kk < BK; kk++) {
            float a0 = As[ty * 4 + 0][kk];
            float a1 = As[ty * 4 + 1][kk];
            float a2 = As[ty * 4 + 2][kk];
            float a3 = As[ty * 4 + 3][kk];
            float4 b4 = *reinterpret_cast<const float4*>(&Bs[kk][tx * 4]);
            acc[0][0] = fmaf(a0, b4.x, acc[0][0]); acc[0][1] = fmaf(a0, b4.y, acc[0][1]);
            acc[0][2] = fmaf(a0, b4.z, acc[0][2]); acc[0][3] = fmaf(a0, b4.w, acc[0][3]);
            acc[1][0] = fmaf(a1, b4.x, acc[1][0]); acc[1][1] = fmaf(a1, b4.y, acc[1][1]);
            acc[1][2] = fmaf(a1, b4.z, acc[1][2]); acc[1][3] = fmaf(a1, b4.w, acc[1][3]);
            acc[2][0] = fmaf(a2, b4.x, acc[2][0]); acc[2][1] = fmaf(a2, b4.y, acc[2][1]);
            acc[2][2] = fmaf(a2, b4.z, acc[2][2]); acc[2][3] = fmaf(a2, b4.w, acc[2][3]);
            acc[3][0] = fmaf(a3, b4.x, acc[3][0]); acc[3][1] = fmaf(a3, b4.y, acc[3][1]);
            acc[3][2] = fmaf(a3, b4.z, acc[3][2]); acc[3][3] = fmaf(a3, b4.w, acc[3][3]);
        }
        __syncthreads();
    }
#pragma unroll
    for (int i = 0; i < 4; i++) {
        int gr = m0 + ty * 4 + i;
        if (gr < M) {
#pragma unroll
            for (int j = 0; j < 4; j++) {
                int gn = n0 + tx * 4 + j;
                if (gn < N) C[(size_t)gr * N + gn] = acc[i][j] + bias[gn];
            }
        }
    }
}

__global__ void k_gemm_Zf(const float* __restrict__ W, const float* __restrict__ b) {
    gemm_body<S_LEN, Z_DIM, D_DIM, 0>(g_emb, W, b, g_Zf);
}
__global__ void k_gemm_Zb(const float* __restrict__ W, const float* __restrict__ b) {
    gemm_body<S_LEN, Z_DIM, D_DIM, 1>(g_emb, W, b, g_Zb);
}
__global__ void k_gemm_P(const float* __restrict__ W, const float* __restrict__ b) {
    gemm_body<S_LEN, HH, HH, 0>(g_hidden, W, b, g_Pout);
}

// ---------------- LSTM recurrence: 2 clusters (fwd/bwd) of 6 CTAs ----------------
// TPO=2: each gate-output computed by 2 lanes (84 padded h-slots each); each warp
// owns 4 units (25th unit alone in warp 6). Per step the warp's 4 h values are
// gathered to lane 0 (3 shfls) and broadcast as ONE st.async.v4.b32 (16B) per peer
// carrying the mbarrier tx credit. 42 tx events per consumer per step (vs 78).
// h layout: per-source region stride 28 floats (112B, 16B-aligned v4 targets).
#define GCL    6
#define UPC    25
#define OPC    100               // gate outputs per CTA
#define SRC_STRIDE 28            // padded slots per source CTA (112 bytes)
#define HPAD   168               // 6*28 floats
#define KCH    84                // slots per lane (2 lanes * 84 = 168)
#define KP2    42                // packed f32x2 per lane
#define LSTM_T 224               // 7 warps (200 active threads)
#define EXP_TX 600               // bytes per consumer per step: 6 * (6*16 + 4)

__global__ __launch_bounds__(LSTM_T, 1) __cluster_dims__(GCL, 1, 1)
void k_lstm(const float* __restrict__ Uf, const float* __restrict__ Ub) {
    cg::cluster_group cluster = cg::this_cluster();
    const int rank = (int)cluster.block_rank();
    const int dir = blockIdx.x / GCL;  // 0 = fwd, 1 = bwd
    const float* __restrict__ Z = (dir == 0) ? g_Zf : g_Zb;
    const float* __restrict__ U = (dir == 0) ? Uf : Ub;

    __shared__ __align__(16) float h_sh[2][HPAD];  // double-buffered padded h
    __shared__ __align__(8) uint64_t mb[2];

    const int tid = threadIdx.x;
    const int warp = tid >> 5;                // 0..6
    const int lane = tid & 31;
    const int o_local = tid >> 1;             // 0..111
    const int lg = tid & 1;                   // lane within output pair
    const bool active = (o_local < OPC);
    const int u = o_local >> 2;               // unit 0..24
    const int g = o_local & 3;                // gate 0..3 (i,f,g,o)
    const int uw = u & 3;                     // unit within warp
    const int ubase = uw << 3;                // unit's lane base (0,8,16,24)
    int j = g * HU + rank * UPC + u;          // column in [0,600)
    if (!active) j = 0;
    const int k0 = lg * KCH;                  // padded-slot base for this lane
    const bool owner = active && ((lane & 7) == 0);   // lg==0 && g==0
    const bool sender = active && (lane == 0);        // one per warp

    // U slice in registers, indexed by PADDED slot: slot s -> source rank s/28,
    // local unit s%28 (s%28 >= 25 is padding; U=0, h stays 0 there).
    unsigned long long U2[KP2];
#pragma unroll
    for (int i = 0; i < KP2; i++) {
        float v[2];
#pragma unroll
        for (int q = 0; q < 2; q++) {
            int s = k0 + 2 * i + q;
            int sr = s / SRC_STRIDE, su = s - sr * SRC_STRIDE;
            bool valid = active && sr < GCL && su < UPC;
            v[q] = valid ? U[(size_t)(sr * UPC + su) * Z_DIM + j] : 0.f;
        }
        U2[i] = pack2(v[0], v[1]);
    }

    for (int k = tid; k < 2 * HPAD; k += blockDim.x) (&h_sh[0][0])[k] = 0.f;

    const uint32_t m0 = smem_u32(&mb[0]), m1 = smem_u32(&mb[1]);
    const uint32_t hbase = smem_u32(&h_sh[0][0]);
    if (tid == 0) {
        mbar_init(m0, 1);  // sole arrival = the expect_tx post; completion via tx bytes
        mbar_init(m1, 1);
    }

    // sender-side peer addresses: data slot (this CTA's region, this warp's 16B) + mbars
    uint32_t pb[GCL], pm0[GCL], pm1[GCL];
    if (sender) {
        const uint32_t slot_off = (uint32_t)(rank * SRC_STRIDE + 4 * warp) * 4u;  // 16B-aligned
#pragma unroll
        for (int r = 0; r < GCL; r++) {
            pb[r] = mapa_shared(hbase, r) + slot_off;
            pm0[r] = mapa_shared(m0, r);
            pm1[r] = mapa_shared(m1, r);
        }
    }

    float c = 0.f;
    int ph0 = 0, ph1 = 0;

    cluster.sync();  // mbar init + zeroed buffers visible cluster-wide

    float zcur = (active && lg == 0) ? __ldg(&Z[j]) : 0.f;

    for (int t = 0; t < S_LEN; t++) {
        const int b = t & 1;
        if (t) {
            if (b) {
                if (tid == 0) mbar_expect_tx(m1, EXP_TX);
                mbar_wait(m1, ph1); ph1 ^= 1;
            } else {
                if (tid == 0) mbar_expect_tx(m0, EXP_TX);
                mbar_wait(m0, ph0); ph0 ^= 1;
            }
        }
        // ---- dot over padded h buffer (packed f32x2 FMA, 84 floats per lane) ----
        const ulonglong2* hp = reinterpret_cast<const ulonglong2*>(&h_sh[b][k0]);
        unsigned long long a0 = 0ull, a1 = 0ull;
#pragma unroll
        for (int i = 0; i < KP2 / 2; i++) {
            ulonglong2 hv = hp[i];
            fma_f32x2(a0, U2[2 * i + 0], hv.x, a0);
            fma_f32x2(a1, U2[2 * i + 1], hv.y, a1);
        }
        unsigned long long as;
        asm("add.rn.f32x2 %0, %1, %2;" : "=l"(as) : "l"(a0), "l"(a1));
        float acc = __uint_as_float((uint32_t)as) + __uint_as_float((uint32_t)(as >> 32));
        acc += __shfl_xor_sync(0xffffffffu, acc, 1);  // pair reduce -> even lanes
        float zfull = zcur + acc;
        if (active && lg == 0 && t + 1 < S_LEN) zcur = __ldg(&Z[(size_t)(t + 1) * Z_DIM + j]);

        // per-gate activation on even lanes (parallel MUFU, off the owner chain)
        float act = 0.f;
        if (active && lg == 0) act = (g == 2) ? ftanh(zfull) : fsig(zfull);

        // collect activated gates onto the unit's owner lane (ubase: gates at +0,+2,+4,+6)
        float fg = __shfl_sync(0xffffffffu, act, ubase + 2);
        float gg = __shfl_sync(0xffffffffu, act, ubase + 4);
        float og = __shfl_sync(0xffffffffu, act, ubase + 6);

        float hval = 0.f;
        if (owner) {
            c = fg * c + act * gg;
            hval = og * ftanh(c);
            int s_out = (dir == 0) ? t : (S_LEN - 1 - t);
            g_hidden[(size_t)s_out * HH + dir * HU + rank * UPC + u] = hval;
        }
        // gather the warp's 4 unit h values onto lane 0, broadcast as one v4 per peer
        float h1 = __shfl_sync(0xffffffffu, hval, 8);
        float h2 = __shfl_sync(0xffffffffu, hval, 16);
        float h3 = __shfl_sync(0xffffffffu, hval, 24);
        if (sender && t + 1 < S_LEN) {
            const uint32_t boff = (uint32_t)((t + 1) & 1) * (HPAD * 4u);
            if (warp < 6) {
                if ((t + 1) & 1) {
#pragma unroll
                    for (int r = 0; r < GCL; r++)
                        st_async_v4(pb[r] + boff, hval, h1, h2, h3, pm1[r]);
                } else {
#pragma unroll
                    for (int r = 0; r < GCL; r++)
                        st_async_v4(pb[r] + boff, hval, h1, h2, h3, pm0[r]);
                }
            } else {  // warp 6: single unit 24 (slot offset already = rank*28 + 24)
                if ((t + 1) & 1) {
#pragma unroll
                    for (int r = 0; r < GCL; r++) st_async_b32(pb[r] + boff, hval, pm1[r]);
                } else {
#pragma unroll
                    for (int r = 0; r < GCL; r++) st_async_b32(pb[r] + boff, hval, pm0[r]);
                }
            }
        }
    }
}

// ---------------- primary attention (per word) + secondary attention coeff ----------------
__global__ void k_attn(const int* __restrict__ syn, const float* __restrict__ E,
                       const float* __restrict__ Ws, const float* __restrict__ bs) {
    int s = blockIdx.x;
    int tid = threadIdx.x;  // 128
    int warp = tid >> 5, lane = tid & 31;
    __shared__ float sc[NSYN];
    __shared__ int idx[NSYN];
    __shared__ float red[128];
    if (s == 0) {  // zero the H_HAT accumulator (consumed by k_hhat after this kernel)
        for (int k = tid; k < 2 * HH; k += 128) g_HHAT[k] = 0.f;
    }
    if (tid < NSYN) idx[tid] = syn[s * NSYN + tid];
    __syncthreads();
    {
        const float* sy = E + (size_t)idx[warp] * D_DIM;
        const float* po = g_Pout + (size_t)s * HH;
        float d0 = 0.f;
        for (int d = lane; d < D_DIM; d += 32) d0 = fmaf(po[d], sy[d], d0);
#pragma unroll
        for (int o = 16; o; o >>= 1) d0 += __shfl_xor_sync(0xffffffffu, d0, o);
        if (lane == 0) sc[warp] = __expf(d0);
    }
    __syncthreads();
    const float* e0 = E + (size_t)idx[0] * D_DIM;
    const float* e1 = E + (size_t)idx[1] * D_DIM;
    const float* e2 = E + (size_t)idx[2] * D_DIM;
    const float* e3 = E + (size_t)idx[3] * D_DIM;
    float s0 = sc[0], s1 = sc[1], s2 = sc[2], s3 = sc[3];
    float ca = 0.f;
    for (int d = tid; d < D_DIM; d += 128) {
        float md = s0 * e0[d] + s1 * e1[d] + s2 * e2[d] + s3 * e3[d];
        g_m[(size_t)s * D_DIM + d] = md;
        ca = fmaf(md, Ws[HH + d], ca);
        ca = fmaf(g_hidden[(size_t)s * HH + d], Ws[d], ca);
    }
    red[tid] = ca;
    __syncthreads();
    for (int o = 64; o; o >>= 1) {
        if (tid < o) red[tid] += red[tid + o];
        __syncthreads();
    }
    if (tid == 0) g_coeff[s] = __expf(tanhf(red[0] + bs[0]));
}

// ---------------- H_HAT[j] = sum_s coeff[s] * h_hats[s][j]  (parallel over s) ----------------
#define HH_BLOCKS 64
#define HH_SPB (S_LEN / HH_BLOCKS)
__global__ void k_hhat() {
    int jj = threadIdx.x;  // 0..599
    int s0 = blockIdx.x * HH_SPB;
    const float* src = (jj < HH) ? (g_hidden + jj) : (g_m + (jj - HH));
    float acc = 0.f;
#pragma unroll 4
    for (int s = s0; s < s0 + HH_SPB; s++)
        acc = fmaf(g_coeff[s], src[(size_t)s * HH], acc);
    atomicAdd(&g_HHAT[jj], acc);
}

// ---------------- output heads ----------------
__global__ void k_heads(const float* __restrict__ We, const float* __restrict__ be,
                        const float* __restrict__ Wse, const float* __restrict__ bse,
                        float* __restrict__ out) {
    int tid = threadIdx.x;
    if (tid < 8) {
        float a = 0.f;
        for (int jj = 0; jj < 2 * HH; jj++) a = fmaf(g_HHAT[jj], We[jj * 8 + tid], a);
        out[tid] = a + be[tid];
    } else if (tid == 8) {
        float a = 0.f;
        for (int jj = 0; jj < 2 * HH; jj++) a = fmaf(g_HHAT[jj], Wse[jj], a);
        out[8] = a + bse[0];
    }
}

// ---------------- launch ----------------
extern "C" void kernel_launch(void* const* d_in, const int* in_sizes, int n_in,
                              void* d_out, int out_size) {
    const int* sentence = (const int*)d_in[0];
    const int* syn = (const int*)d_in[1];
    const float* E = (const float*)d_in[2];
    const float* W_f = (const float*)d_in[3];
    const float* U_f = (const float*)d_in[4];
    const float* b_f = (const float*)d_in[5];
    const float* W_b = (const float*)d_in[6];
    const float* U_b = (const float*)d_in[7];
    const float* b_b = (const float*)d_in[8];
    const float* W_p = (const float*)d_in[9];
    const float* b_p = (const float*)d_in[10];
    const float* W_s = (const float*)d_in[11];
    const float* b_s = (const float*)d_in[12];
    const float* W_emo = (const float*)d_in[13];
    const float* b_emo = (const float*)d_in[14];
    const float* W_sent = (const float*)d_in[15];
    const float* b_sent = (const float*)d_in[16];
    float* out = (float*)d_out;

    k_gather<<<S_LEN, 128>>>(sentence, E);

    dim3 blk(16, 16);
    dim3 gz((Z_DIM + BN - 1) / BN, (S_LEN + BM - 1) / BM);
    k_gemm_Zf<<<gz, blk>>>(W_f, b_f);
    k_gemm_Zb<<<gz, blk>>>(W_b, b_b);

    k_lstm<<<2 * GCL, LSTM_T>>>(U_f, U_b);

    dim3 gp((HH + BN - 1) / BN, (S_LEN + BM - 1) / BM);
    k_gemm_P<<<gp, blk>>>(W_p, b_p);

    k_attn<<<S_LEN, 128>>>(syn, E, W_s, b_s);
    k_hhat<<<HH_BLOCKS, 2 * HH>>>();
    k_heads<<<1, 32>>>(W_emo, b_emo, W_sent, b_sent, out);
}